// round 2
// baseline (speedup 1.0000x reference)
#include <cuda_runtime.h>

#define HID  64
#define FEAT 9
#define TT   36
#define BLK  128

// ---- shared layout (float offsets) ----
#define OFF_WG     0                  // [64][82][4] interleaved gates = 20992
#define OFF_B4     20992              // [64][4] combined bias = 256
#define OFF_WGH    21248              // [64][9] = 576
#define OFF_BGH    21824              // 64
#define OFF_WHIST  21888              // [9][64] = 576
#define OFF_BHIST  22464              // 9 (+3 pad)
#define OFF_WGXD   22476              // 9 (+3)
#define OFF_BGX    22488              // 9 (+3)
#define OFF_WFEAT  22500              // 81 (+3)
#define OFF_BFEAT  22584              // 9 (+3)
#define OFF_WCOMB  22596              // 162 (+2)
#define OFF_BCOMB  22760              // 9 (+3)
#define OFF_INV    22772              // 36
#define OFF_H      22808              // [128][68]
#define OFF_C      (OFF_H + BLK*68)
#define SMEM_FLOATS (OFF_C + BLK*68)
#define SMEM_BYTES  (SMEM_FLOATS * 4)

__device__ float g_inv_denom[TT];
__device__ float g_partials[1024];

__device__ __forceinline__ float fsigmoid(float x) {
    return __fdividef(1.0f, 1.0f + __expf(-x));
}
__device__ __forceinline__ float ftanhx(float x) {
    float e = __expf(2.0f * x);
    return 1.0f - __fdividef(2.0f, e + 1.0f);
}

// ---- per-timestep mask-sum reciprocal: one block per t ----
__global__ void denom_kernel(const float* __restrict__ masks, int B) {
    int t = blockIdx.x;
    float s = 0.0f;
    int n = B * FEAT;
    for (int i = threadIdx.x; i < n; i += blockDim.x) {
        int b = i / FEAT;
        int f = i - b * FEAT;
        s += masks[(size_t)b * (TT * FEAT) + t * FEAT + f];
    }
    __shared__ float red[8];
    #pragma unroll
    for (int o = 16; o; o >>= 1) s += __shfl_down_sync(~0u, s, o);
    if ((threadIdx.x & 31) == 0) red[threadIdx.x >> 5] = s;
    __syncthreads();
    if (threadIdx.x < 8) {
        s = red[threadIdx.x];
        #pragma unroll
        for (int o = 4; o; o >>= 1) s += __shfl_down_sync(0xff, s, o);
        if (threadIdx.x == 0) g_inv_denom[t] = 1.0f / (s + 1e-5f);
    }
}

__global__ void __launch_bounds__(BLK)
rits_main_kernel(const float* __restrict__ values,
                 const float* __restrict__ masks,
                 const float* __restrict__ deltas,
                 const float* __restrict__ Wgh, const float* __restrict__ bgh,
                 const float* __restrict__ Wgx, const float* __restrict__ bgx,
                 const float* __restrict__ Whist, const float* __restrict__ bhist,
                 const float* __restrict__ Wfeat, const float* __restrict__ bfeat,
                 const float* __restrict__ Wcomb, const float* __restrict__ bcomb,
                 const float* __restrict__ Wih, const float* __restrict__ Whh,
                 const float* __restrict__ bih, const float* __restrict__ bhh,
                 float* __restrict__ out, int B) {
    extern __shared__ float s[];
    const int tid = threadIdx.x;
    const int b = blockIdx.x * BLK + tid;

    // ---- stage weights into shared ----
    for (int idx = tid; idx < 64 * 82 * 4; idx += BLK) {
        int g = idx & 3;
        int jk = idx >> 2;
        int j = jk / 82, k = jk - j * 82;
        int row = g * HID + j;
        s[OFF_WG + idx] = (k < 18) ? Wih[row * 18 + k] : Whh[row * HID + (k - 18)];
    }
    for (int idx = tid; idx < 256; idx += BLK) {
        int g = idx & 3, j = idx >> 2;
        s[OFF_B4 + idx] = bih[g * HID + j] + bhh[g * HID + j];
    }
    for (int idx = tid; idx < 576; idx += BLK) {
        s[OFF_WGH + idx] = Wgh[idx];
        s[OFF_WHIST + idx] = Whist[idx];
    }
    // W_comb has 162 elements (> BLK): MUST be a strided loop (R1 bug fix)
    for (int idx = tid; idx < 162; idx += BLK) s[OFF_WCOMB + idx] = Wcomb[idx];
    if (tid < 64) s[OFF_BGH + tid] = bgh[tid];
    if (tid < 9) {
        s[OFF_BHIST + tid] = bhist[tid];
        s[OFF_WGXD + tid] = Wgx[tid * FEAT + tid];
        s[OFF_BGX + tid] = bgx[tid];
        s[OFF_BFEAT + tid] = bfeat[tid];
        s[OFF_BCOMB + tid] = bcomb[tid];
    }
    if (tid < 81) {
        int f = tid / 9, f2 = tid - f * 9;
        s[OFF_WFEAT + tid] = (f == f2) ? 0.0f : Wfeat[tid];
    }
    if (tid < TT) s[OFF_INV + tid] = g_inv_denom[tid];

    float* myh = s + OFF_H + tid * 68;
    float* myc = s + OFF_C + tid * 68;
    #pragma unroll
    for (int k = 0; k < 68; k++) { myh[k] = 0.0f; myc[k] = 0.0f; }
    __syncthreads();

    float loss = 0.0f;
    if (b < B) {
        const float* xb = values + (size_t)b * (TT * FEAT);
        const float* mb = masks + (size_t)b * (TT * FEAT);
        const float* db = deltas + (size_t)b * (TT * FEAT);
        float* ob = out + 1 + (size_t)b * (TT * FEAT);

        for (int t = 0; t < TT; t++) {
            float x[9], m[9], d[9];
            #pragma unroll
            for (int f = 0; f < 9; f++) {
                x[f] = xb[t * 9 + f];
                m[f] = mb[t * 9 + f];
                d[f] = db[t * 9 + f];
            }

            // gamma_h decay applied to h in shared
            #pragma unroll 4
            for (int j = 0; j < 64; j++) {
                const float* w = s + OFF_WGH + j * 9;
                float a = s[OFF_BGH + j];
                #pragma unroll
                for (int f = 0; f < 9; f++) a = fmaf(d[f], w[f], a);
                myh[j] *= __expf(-fmaxf(a, 0.0f));
            }

            // hoist decayed h to registers (conflict-free LDS.128)
            float hreg[64];
            #pragma unroll
            for (int k = 0; k < 16; k++) {
                float4 v = *(const float4*)(myh + 4 * k);
                hreg[4 * k]     = v.x;
                hreg[4 * k + 1] = v.y;
                hreg[4 * k + 2] = v.z;
                hreg[4 * k + 3] = v.w;
            }

            // history regression x_h = h @ W_hist^T + b
            float xh[9];
            #pragma unroll
            for (int f = 0; f < 9; f++) {
                const float4* w = (const float4*)(s + OFF_WHIST + f * 64);
                float a0 = s[OFF_BHIST + f], a1 = 0.0f, a2 = 0.0f, a3 = 0.0f;
                #pragma unroll
                for (int k = 0; k < 16; k++) {
                    float4 wv = w[k];
                    a0 = fmaf(hreg[4 * k],     wv.x, a0);
                    a1 = fmaf(hreg[4 * k + 1], wv.y, a1);
                    a2 = fmaf(hreg[4 * k + 2], wv.z, a2);
                    a3 = fmaf(hreg[4 * k + 3], wv.w, a3);
                }
                xh[f] = (a0 + a1) + (a2 + a3);
            }

            float xc[9], gx[9];
            #pragma unroll
            for (int f = 0; f < 9; f++) {
                xc[f] = m[f] * x[f] + (1.0f - m[f]) * xh[f];
                gx[f] = __expf(-fmaxf(fmaf(d[f], s[OFF_WGXD + f], s[OFF_BGX + f]), 0.0f));
            }

            float inp[18];
            float lsum = 0.0f;
            #pragma unroll
            for (int f = 0; f < 9; f++) {
                const float* wf = s + OFF_WFEAT + f * 9;
                float zh = s[OFF_BFEAT + f];
                #pragma unroll
                for (int k = 0; k < 9; k++) zh = fmaf(xc[k], wf[k], zh);
                const float* wc = s + OFF_WCOMB + f * 18;
                float al = s[OFF_BCOMB + f];
                #pragma unroll
                for (int k = 0; k < 9; k++) al = fmaf(gx[k], wc[k], al);
                #pragma unroll
                for (int k = 0; k < 9; k++) al = fmaf(m[k], wc[9 + k], al);
                float ch = al * zh + (1.0f - al) * xh[f];
                lsum += m[f] * (fabsf(x[f] - xh[f]) + fabsf(x[f] - zh) + fabsf(x[f] - ch));
                float c_c = m[f] * x[f] + (1.0f - m[f]) * ch;
                ob[t * 9 + f] = c_c;
                inp[f] = c_c;
                inp[9 + f] = m[f];
            }
            loss = fmaf(lsum, s[OFF_INV + t], loss);

            // LSTM gates: per unit j, 4 gates via interleaved [j][k][gate] weights
            #pragma unroll 1
            for (int j = 0; j < 64; j++) {
                const float4* wj = (const float4*)(s + OFF_WG + j * 328);
                float4 bb = *(const float4*)(s + OFF_B4 + j * 4);
                float ai = bb.x, af = bb.y, ag = bb.z, ao = bb.w;
                #pragma unroll
                for (int k = 0; k < 18; k++) {
                    float4 w = wj[k];
                    ai = fmaf(inp[k], w.x, ai);
                    af = fmaf(inp[k], w.y, af);
                    ag = fmaf(inp[k], w.z, ag);
                    ao = fmaf(inp[k], w.w, ao);
                }
                #pragma unroll
                for (int k = 0; k < 64; k++) {
                    float4 w = wj[18 + k];
                    ai = fmaf(hreg[k], w.x, ai);
                    af = fmaf(hreg[k], w.y, af);
                    ag = fmaf(hreg[k], w.z, ag);
                    ao = fmaf(hreg[k], w.w, ao);
                }
                float cn = fsigmoid(af) * myc[j] + fsigmoid(ai) * ftanhx(ag);
                myc[j] = cn;
                myh[j] = fsigmoid(ao) * ftanhx(cn);
            }
        }
    }

    // deterministic block reduction of loss
    #pragma unroll
    for (int o = 16; o; o >>= 1) loss += __shfl_down_sync(~0u, loss, o);
    __shared__ float red[4];
    if ((tid & 31) == 0) red[tid >> 5] = loss;
    __syncthreads();
    if (tid == 0) g_partials[blockIdx.x] = (red[0] + red[1]) + (red[2] + red[3]);
}

__global__ void finalize_kernel(float* __restrict__ out, int nblocks) {
    float sv = 0.0f;
    for (int i = threadIdx.x; i < nblocks; i += 256) sv += g_partials[i];
    __shared__ float red[8];
    #pragma unroll
    for (int o = 16; o; o >>= 1) sv += __shfl_down_sync(~0u, sv, o);
    if ((threadIdx.x & 31) == 0) red[threadIdx.x >> 5] = sv;
    __syncthreads();
    if (threadIdx.x < 8) {
        sv = red[threadIdx.x];
        #pragma unroll
        for (int o = 4; o; o >>= 1) sv += __shfl_down_sync(0xff, sv, o);
        if (threadIdx.x == 0) out[0] = sv * (1.0f / (float)TT);
    }
}

extern "C" void kernel_launch(void* const* d_in, const int* in_sizes, int n_in,
                              void* d_out, int out_size) {
    const float* values = (const float*)d_in[0];
    const float* masks  = (const float*)d_in[1];
    const float* deltas = (const float*)d_in[2];
    const float* Wgh   = (const float*)d_in[3];
    const float* bgh   = (const float*)d_in[4];
    const float* Wgx   = (const float*)d_in[5];
    const float* bgx   = (const float*)d_in[6];
    const float* Whist = (const float*)d_in[7];
    const float* bhist = (const float*)d_in[8];
    const float* Wfeat = (const float*)d_in[9];
    const float* bfeat = (const float*)d_in[10];
    const float* Wcomb = (const float*)d_in[11];
    const float* bcomb = (const float*)d_in[12];
    const float* Wih   = (const float*)d_in[13];
    const float* Whh   = (const float*)d_in[14];
    const float* bih   = (const float*)d_in[15];
    const float* bhh   = (const float*)d_in[16];
    float* out = (float*)d_out;

    int B = in_sizes[0] / (TT * FEAT);
    int nb = (B + BLK - 1) / BLK;

    cudaFuncSetAttribute(rits_main_kernel,
                         cudaFuncAttributeMaxDynamicSharedMemorySize, SMEM_BYTES);

    denom_kernel<<<TT, 256>>>(masks, B);
    rits_main_kernel<<<nb, BLK, SMEM_BYTES>>>(
        values, masks, deltas, Wgh, bgh, Wgx, bgx, Whist, bhist,
        Wfeat, bfeat, Wcomb, bcomb, Wih, Whh, bih, bhh, out, B);
    finalize_kernel<<<1, 256>>>(out, nb);
}